// round 13
// baseline (speedup 1.0000x reference)
#include <cuda_runtime.h>
#include <cuda_bf16.h>
#include <cstdint>
#include <math.h>

#define BATCH 4
#define SEQ 4096
#define DIM 512
#define QK 128
#define LN_EPS 1e-5f
#define NJT 32

// q/k stored as TILED-SWIZZLED 32KB images: tile t = rows [t*128, t*128+128),
// byte offset within tile = swoff(row&127, e>>3) + (e&7)*2. Tile index = globalrow>>7.
__device__ __align__(128) __nv_bfloat16 g_qh[BATCH * SEQ * QK];
__device__ __align__(128) __nv_bfloat16 g_ql[BATCH * SEQ * QK];
__device__ __align__(128) __nv_bfloat16 g_kh[BATCH * SEQ * QK];
__device__ __align__(128) __nv_bfloat16 g_kl[BATCH * SEQ * QK];
__device__ __align__(128) __nv_bfloat16 g_wh[QK * DIM];     // (lnw ⊙ W) hi
__device__ __align__(128) __nv_bfloat16 g_wl[QK * DIM];     // (lnw ⊙ W) lo
__device__ __align__(128) __nv_bfloat16 g_xh[BATCH * SEQ * DIM];
__device__ __align__(128) __nv_bfloat16 g_xl[BATCH * SEQ * DIM];
__device__ float g_mu[BATCH * SEQ];
__device__ float g_rs[BATCH * SEQ];
__device__ float g_c1[QK];
__device__ float g_c2[QK];

// ---------------------------------------------------------------------------
// common helpers
// ---------------------------------------------------------------------------
__device__ __forceinline__ uint32_t smem_u32(const void* p) {
    uint32_t a;
    asm("{ .reg .u64 t; cvta.to.shared.u64 t, %1; cvt.u32.u64 %0, t; }" : "=r"(a) : "l"(p));
    return a;
}
__device__ __forceinline__ void cpasync16(uint32_t dst, const void* src) {
    asm volatile("cp.async.cg.shared.global [%0], [%1], 16;"
                 :: "r"(dst), "l"(__cvta_generic_to_global(src)));
}
__device__ __forceinline__ void ldsm4(uint32_t a, uint32_t& r0, uint32_t& r1,
                                      uint32_t& r2, uint32_t& r3) {
    asm volatile("ldmatrix.sync.aligned.m8n8.x4.shared.b16 {%0,%1,%2,%3}, [%4];"
                 : "=r"(r0), "=r"(r1), "=r"(r2), "=r"(r3) : "r"(a));
}
__device__ __forceinline__ void mma16816(float* c,
                                         const uint32_t* a, uint32_t b0, uint32_t b1) {
    asm volatile("mma.sync.aligned.m16n8k16.row.col.f32.bf16.bf16.f32 "
                 "{%0,%1,%2,%3}, {%4,%5,%6,%7}, {%8,%9}, {%0,%1,%2,%3};"
                 : "+f"(c[0]), "+f"(c[1]), "+f"(c[2]), "+f"(c[3])
                 : "r"(a[0]), "r"(a[1]), "r"(a[2]), "r"(a[3]), "r"(b0), "r"(b1));
}
// swizzled offset: row stride 256B (128 bf16), 16 chunks of 16B, chunk ^= row&7
__device__ __forceinline__ uint32_t swoff(int r, int ch) {
    return (uint32_t)r * 256u + (uint32_t)((ch ^ (r & 7)) << 4);
}
// bulk 32KB gmem->smem with mbarrier completion
__device__ __forceinline__ void bulk32k(uint32_t dst, const void* src, uint32_t mbar) {
    asm volatile("cp.async.bulk.shared::cta.global.mbarrier::complete_tx::bytes "
                 "[%0], [%1], 32768, [%2];"
                 :: "r"(dst), "l"(__cvta_generic_to_global(src)), "r"(mbar) : "memory");
}
#define MBARRIER_INIT(addr, cnt) \
    asm volatile("mbarrier.init.shared.b64 [%0], %1;" :: "r"(addr), "r"(cnt) : "memory")
#define MBARRIER_EXPECT_TX(addr, bytes) \
    asm volatile("mbarrier.arrive.expect_tx.shared.b64 _, [%0], %1;" \
                 :: "r"(addr), "r"(bytes) : "memory")
#define MBARRIER_WAIT_PARITY(mbar_smem_addr, phase_parity) do { \
    uint32_t _mbar = (uint32_t)(mbar_smem_addr); \
    uint32_t _parity = (uint32_t)(phase_parity); \
    uint32_t _done; \
    asm volatile("{\n\t.reg .pred p;\n\tmbarrier.try_wait.parity.acquire.cta.shared::cta.b64 p, [%1], %2;\n\tselp.b32 %0, 1, 0, p;\n\t}" \
        : "=r"(_done) : "r"(_mbar), "r"(_parity) : "memory"); \
    if (!_done) { \
        asm volatile("{\n\t.reg .pred P1;\n\tWAIT_LOOP_%=:\n\tmbarrier.try_wait.parity.acquire.cta.shared::cta.b64 P1, [%0], %1, 0x989680;\n\t@P1 bra.uni WAIT_DONE_%=;\n\tbra.uni WAIT_LOOP_%=;\n\tWAIT_DONE_%=:\n\t}" \
            :: "r"(_mbar), "r"(_parity) : "memory"); \
    } \
} while (0)
#define FENCE_ASYNC_SHARED() asm volatile("fence.proxy.async.shared::cta;" ::: "memory")

// ---------------------------------------------------------------------------
// Kernel 0a: fold lnw into W, split hi/lo, reduce c1, c2.
// ---------------------------------------------------------------------------
__global__ __launch_bounds__(128) void wsplit_kernel(
    const float* __restrict__ w,
    const float* __restrict__ lnw, const float* __restrict__ lnb)
{
    const int e = blockIdx.x, t = threadIdx.x;
    float4 v  = ((const float4*)(w + (size_t)e * DIM))[t];
    float4 lw = ((const float4*)lnw)[t];
    float4 lb = ((const float4*)lnb)[t];
    float sv[4] = { v.x * lw.x, v.y * lw.y, v.z * lw.z, v.w * lw.w };
    float s1 = sv[0] + sv[1] + sv[2] + sv[3];
    float s2 = v.x * lb.x + v.y * lb.y + v.z * lb.z + v.w * lb.w;

    __nv_bfloat16 h4[4], l4[4];
#pragma unroll
    for (int j = 0; j < 4; ++j) {
        h4[j] = __float2bfloat16(sv[j]);
        l4[j] = __float2bfloat16(sv[j] - __bfloat162float(h4[j]));
    }
    *(uint2*)(g_wh + (size_t)e * DIM + t * 4) = *(uint2*)h4;
    *(uint2*)(g_wl + (size_t)e * DIM + t * 4) = *(uint2*)l4;

#pragma unroll
    for (int o = 16; o > 0; o >>= 1) {
        s1 += __shfl_xor_sync(0xFFFFFFFFu, s1, o);
        s2 += __shfl_xor_sync(0xFFFFFFFFu, s2, o);
    }
    __shared__ float r1[4], r2[4];
    if ((t & 31) == 0) { r1[t >> 5] = s1; r2[t >> 5] = s2; }
    __syncthreads();
    if (t == 0) {
        g_c1[e] = r1[0] + r1[1] + r1[2] + r1[3];
        g_c2[e] = r2[0] + r2[1] + r2[2] + r2[3];
    }
}

// ---------------------------------------------------------------------------
// Kernel 0b: split raw x into bf16 hi/lo + LN stats. One warp per row.
// ---------------------------------------------------------------------------
__global__ __launch_bounds__(256) void xsplit_kernel(const float* __restrict__ x)
{
    const int tid = threadIdx.x, wid = tid >> 5, lane = tid & 31;
    const size_t row = (size_t)blockIdx.x * 8 + wid;
    const float4* xr = (const float4*)(x + row * DIM);

    float4 v[4];
    float s = 0.f, sq = 0.f;
#pragma unroll
    for (int i = 0; i < 4; ++i) {
        v[i] = xr[lane + 32 * i];
        s  += v[i].x + v[i].y + v[i].z + v[i].w;
        sq += v[i].x * v[i].x + v[i].y * v[i].y + v[i].z * v[i].z + v[i].w * v[i].w;
    }
#pragma unroll
    for (int o = 16; o > 0; o >>= 1) {
        s  += __shfl_xor_sync(0xFFFFFFFFu, s,  o);
        sq += __shfl_xor_sync(0xFFFFFFFFu, sq, o);
    }
    if (lane == 0) {
        float mu  = s * (1.f / DIM);
        float var = sq * (1.f / DIM) - mu * mu;
        g_mu[row] = mu;
        g_rs[row] = rsqrtf(var + LN_EPS);
    }
#pragma unroll
    for (int i = 0; i < 4; ++i) {
        float vv[4] = { v[i].x, v[i].y, v[i].z, v[i].w };
        __nv_bfloat16 h4[4], l4[4];
#pragma unroll
        for (int j = 0; j < 4; ++j) {
            h4[j] = __float2bfloat16(vv[j]);
            l4[j] = __float2bfloat16(vv[j] - __bfloat162float(h4[j]));
        }
        size_t off = row * DIM + (size_t)(lane + 32 * i) * 4;
        *(uint2*)(g_xh + off) = *(uint2*)h4;
        *(uint2*)(g_xl + off) = *(uint2*)l4;
    }
}

// ---------------------------------------------------------------------------
// Kernel 1: pure-GEMM qk, tiled-swizzled q/k output (unchanged from R12).
// ---------------------------------------------------------------------------
#define QSA0 0
#define QSW0 65536
#define QK_SMEM 196608

__global__ __launch_bounds__(256, 1) void qk_kernel(
    const float* __restrict__ bq,
    const float* __restrict__ gamma, const float* __restrict__ beta)
{
    extern __shared__ char sm[];
    const uint32_t sb = smem_u32(sm);
    const int tid = threadIdx.x, wid = tid >> 5, lane = tid & 31;
    const int row0 = blockIdx.x * 64;

#pragma unroll
    for (int s = 0; s < 2; ++s) {
#pragma unroll
        for (int i = 0; i < 4; ++i) {
            int idx = tid + 256 * i;
            int r = idx >> 4, ch = idx & 15;
            cpasync16(sb + QSA0 + s * 32768 + swoff(r, ch),
                      g_xh + (size_t)(row0 + r) * DIM + s * 128 + ch * 8);
            cpasync16(sb + QSA0 + s * 32768 + 16384 + swoff(r, ch),
                      g_xl + (size_t)(row0 + r) * DIM + s * 128 + ch * 8);
        }
#pragma unroll
        for (int i = 0; i < 8; ++i) {
            int idx = tid + 256 * i;
            int r = idx >> 4, ch = idx & 15;
            cpasync16(sb + QSW0 + s * 65536 + swoff(r, ch),
                      g_wh + (size_t)r * DIM + s * 128 + ch * 8);
            cpasync16(sb + QSW0 + s * 65536 + 32768 + swoff(r, ch),
                      g_wl + (size_t)r * DIM + s * 128 + ch * 8);
        }
        asm volatile("cp.async.commit_group;" ::: "memory");
    }

    const int wm0 = (wid & 1) * 32;
    const int wn0 = (wid >> 1) * 32;
    const int a_r  = wm0 + (lane & 15);
    const int a_cb = lane >> 4;
    const int b_n  = wn0 + (lane & 7) + ((lane & 16) >> 1);
    const int b_cb = (lane >> 3) & 1;

    float acc[2][4][4];
#pragma unroll
    for (int mt = 0; mt < 2; ++mt)
#pragma unroll
        for (int n8 = 0; n8 < 4; ++n8)
#pragma unroll
            for (int v = 0; v < 4; ++v) acc[mt][n8][v] = 0.f;

#pragma unroll 1
    for (int c = 0; c < 4; ++c) {
        const int s = c & 1;
        asm volatile("cp.async.wait_group 1;" ::: "memory");
        __syncthreads();

        const uint32_t sAh = sb + QSA0 + s * 32768;
        const uint32_t sAl = sAh + 16384;
        const uint32_t sWh = sb + QSW0 + s * 65536;
        const uint32_t sWl = sWh + 32768;

#pragma unroll
        for (int ks = 0; ks < 8; ++ks) {
            uint32_t ah[2][4], al[2][4];
#pragma unroll
            for (int mt = 0; mt < 2; ++mt) {
                int r = a_r + mt * 16;
                ldsm4(sAh + swoff(r, ks * 2 + a_cb), ah[mt][0], ah[mt][1], ah[mt][2], ah[mt][3]);
                ldsm4(sAl + swoff(r, ks * 2 + a_cb), al[mt][0], al[mt][1], al[mt][2], al[mt][3]);
            }
            uint32_t bh[2][4], bl[2][4];
#pragma unroll
            for (int nb = 0; nb < 2; ++nb) {
                int n = b_n + nb * 16;
                ldsm4(sWh + swoff(n, ks * 2 + b_cb), bh[nb][0], bh[nb][1], bh[nb][2], bh[nb][3]);
                ldsm4(sWl + swoff(n, ks * 2 + b_cb), bl[nb][0], bl[nb][1], bl[nb][2], bl[nb][3]);
            }
#pragma unroll
            for (int mt = 0; mt < 2; ++mt)
#pragma unroll
                for (int n8 = 0; n8 < 4; ++n8) {
                    const int nb = n8 >> 1, hf = (n8 & 1) * 2;
                    mma16816(acc[mt][n8], ah[mt], bh[nb][hf], bh[nb][hf + 1]);
                    mma16816(acc[mt][n8], ah[mt], bl[nb][hf], bl[nb][hf + 1]);
                    mma16816(acc[mt][n8], al[mt], bh[nb][hf], bh[nb][hf + 1]);
                }
        }
        __syncthreads();

        if (c + 2 < 4) {
#pragma unroll
            for (int i = 0; i < 4; ++i) {
                int idx = tid + 256 * i;
                int r = idx >> 4, ch = idx & 15;
                cpasync16(sAh + swoff(r, ch),
                          g_xh + (size_t)(row0 + r) * DIM + (c + 2) * 128 + ch * 8);
                cpasync16(sAl + swoff(r, ch),
                          g_xl + (size_t)(row0 + r) * DIM + (c + 2) * 128 + ch * 8);
            }
#pragma unroll
            for (int i = 0; i < 8; ++i) {
                int idx = tid + 256 * i;
                int r = idx >> 4, ch = idx & 15;
                cpasync16(sWh + swoff(r, ch), g_wh + (size_t)r * DIM + (c + 2) * 128 + ch * 8);
                cpasync16(sWl + swoff(r, ch), g_wl + (size_t)r * DIM + (c + 2) * 128 + ch * 8);
            }
        }
        asm volatile("cp.async.commit_group;" ::: "memory");
    }

    float rsv[2][2], muv[2][2];
#pragma unroll
    for (int mt = 0; mt < 2; ++mt)
#pragma unroll
        for (int half = 0; half < 2; ++half) {
            int row = row0 + wm0 + mt * 16 + (lane >> 2) + half * 8;
            rsv[mt][half] = g_rs[row];
            muv[mt][half] = g_mu[row];
        }

#pragma unroll
    for (int n8 = 0; n8 < 4; ++n8) {
        int e0 = wn0 + n8 * 8 + (lane & 3) * 2;
        float c10 = g_c1[e0],          c11 = g_c1[e0 + 1];
        float c20 = g_c2[e0],          c21 = g_c2[e0 + 1];
        float bb0 = bq[e0],            bb1 = bq[e0 + 1];
        float g00 = gamma[e0],         g01 = gamma[e0 + 1];
        float b00 = beta[e0],          b01 = beta[e0 + 1];
        float g10 = gamma[QK + e0],    g11 = gamma[QK + e0 + 1];
        float b10 = beta[QK + e0],     b11 = beta[QK + e0 + 1];
#pragma unroll
        for (int mt = 0; mt < 2; ++mt) {
#pragma unroll
            for (int half = 0; half < 2; ++half) {
                int row = row0 + wm0 + mt * 16 + (lane >> 2) + half * 8;
                float rs = rsv[mt][half], mu = muv[mt][half];
                float z0 = rs * (acc[mt][n8][half * 2]     - mu * c10) + c20 + bb0;
                float z1 = rs * (acc[mt][n8][half * 2 + 1] - mu * c11) + c21 + bb1;
                float v0 = z0 / (1.f + expf(-z0));
                float v1 = z1 / (1.f + expf(-z1));
                float q0 = v0 * g00 + b00, q1 = v1 * g01 + b01;
                float k0 = v0 * g10 + b10, k1 = v1 * g11 + b11;
                size_t toff = (size_t)(row >> 7) * 32768;
                uint32_t so = swoff(row & 127, e0 >> 3) + (e0 & 7) * 2;
                __nv_bfloat16 t0, t1;
                t0 = __float2bfloat16(q0); t1 = __float2bfloat16(q1);
                *(uint32_t*)((char*)g_qh + toff + so) =
                    (uint32_t)__bfloat16_as_ushort(t0) | ((uint32_t)__bfloat16_as_ushort(t1) << 16);
                __nv_bfloat16 r0 = __float2bfloat16(q0 - __bfloat162float(t0));
                __nv_bfloat16 r1 = __float2bfloat16(q1 - __bfloat162float(t1));
                *(uint32_t*)((char*)g_ql + toff + so) =
                    (uint32_t)__bfloat16_as_ushort(r0) | ((uint32_t)__bfloat16_as_ushort(r1) << 16);
                t0 = __float2bfloat16(k0); t1 = __float2bfloat16(k1);
                *(uint32_t*)((char*)g_kh + toff + so) =
                    (uint32_t)__bfloat16_as_ushort(t0) | ((uint32_t)__bfloat16_as_ushort(t1) << 16);
                r0 = __float2bfloat16(k0 - __bfloat162float(t0));
                r1 = __float2bfloat16(k1 - __bfloat162float(t1));
                *(uint32_t*)((char*)g_kl + toff + so) =
                    (uint32_t)__bfloat16_as_ushort(r0) | ((uint32_t)__bfloat16_as_ushort(r1) << 16);
            }
        }
    }
}

// ---------------------------------------------------------------------------
// Kernel 2: strip-persistent attn, bulk loads, REGISTER-PIPELINED fragments.
// ---------------------------------------------------------------------------
#define SA_HI 0
#define SA_LO 32768
#define SB0   65536
#define SMB   196608
#define ATT_SMEM (196608 + 64)

struct Frag { uint32_t ah[2][4], al[2][4], bh[2][4], bl[2][4]; };

__device__ __forceinline__ void load_frag(Frag& f, uint32_t sAh, uint32_t sAl,
                                          uint32_t sBh, uint32_t sBl,
                                          int a_r, int a_cb, int b_n, int b_cb, int ks) {
#pragma unroll
    for (int mt = 0; mt < 2; ++mt) {
        int r = a_r + mt * 16;
        ldsm4(sAh + swoff(r, ks * 2 + a_cb), f.ah[mt][0], f.ah[mt][1], f.ah[mt][2], f.ah[mt][3]);
        ldsm4(sAl + swoff(r, ks * 2 + a_cb), f.al[mt][0], f.al[mt][1], f.al[mt][2], f.al[mt][3]);
    }
#pragma unroll
    for (int nb = 0; nb < 2; ++nb) {
        int n = b_n + nb * 16;
        ldsm4(sBh + swoff(n, ks * 2 + b_cb), f.bh[nb][0], f.bh[nb][1], f.bh[nb][2], f.bh[nb][3]);
        ldsm4(sBl + swoff(n, ks * 2 + b_cb), f.bl[nb][0], f.bl[nb][1], f.bl[nb][2], f.bl[nb][3]);
    }
}
__device__ __forceinline__ void mma_frag(float (*acc)[4][4], const Frag& f) {
#pragma unroll
    for (int mt = 0; mt < 2; ++mt)
#pragma unroll
        for (int n8 = 0; n8 < 4; ++n8) {
            const int nb = n8 >> 1, hf = (n8 & 1) * 2;
            mma16816(acc[mt][n8], f.ah[mt], f.bh[nb][hf], f.bh[nb][hf + 1]);
            mma16816(acc[mt][n8], f.ah[mt], f.bl[nb][hf], f.bl[nb][hf + 1]);
            mma16816(acc[mt][n8], f.al[mt], f.bh[nb][hf], f.bh[nb][hf + 1]);
        }
}

__global__ __launch_bounds__(512, 1) void attn_kernel(float* __restrict__ out)
{
    extern __shared__ char smem[];
    const uint32_t sb = smem_u32(smem);
    const int tid = threadIdx.x, wid = tid >> 5, lane = tid & 31;
    const int b = blockIdx.y, strip = blockIdx.x;
    const size_t brow = (size_t)b * SEQ + strip * 128;

    const char* qh = (const char*)g_qh + (size_t)(b * 32 + strip) * 32768;
    const char* ql = (const char*)g_ql + (size_t)(b * 32 + strip) * 32768;
    const char* khb = (const char*)g_kh + (size_t)(b * 32) * 32768;
    const char* klb = (const char*)g_kl + (size_t)(b * 32) * 32768;

    const uint32_t mb0 = sb + SMB, mb1 = sb + SMB + 8, mbA = sb + SMB + 16;
    if (tid == 0) {
        MBARRIER_INIT(mb0, 1);
        MBARRIER_INIT(mb1, 1);
        MBARRIER_INIT(mbA, 1);
    }
    FENCE_ASYNC_SHARED();
    __syncthreads();

    if (tid == 0) {
        MBARRIER_EXPECT_TX(mbA, 65536);
        bulk32k(sb + SA_HI, qh, mbA);
        bulk32k(sb + SA_LO, ql, mbA);
        MBARRIER_EXPECT_TX(mb0, 65536);
        bulk32k(sb + SB0,         khb, mb0);
        bulk32k(sb + SB0 + 32768, klb, mb0);
        MBARRIER_EXPECT_TX(mb1, 65536);
        bulk32k(sb + SB0 + 65536,         khb + 32768, mb1);
        bulk32k(sb + SB0 + 65536 + 32768, klb + 32768, mb1);
    }
    MBARRIER_WAIT_PARITY(mbA, 0);

    const int wm0 = (wid & 3) * 32;
    const int wn0 = (wid >> 2) * 32;
    const int a_r  = wm0 + (lane & 15);
    const int a_cb = lane >> 4;
    const int b_n  = wn0 + (lane & 7) + ((lane & 16) >> 1);
    const int b_cb = (lane >> 3) & 1;

    int ph0 = 0, ph1 = 0;
    const uint32_t sAh = sb + SA_HI, sAl = sb + SA_LO;

    for (int jt = 0; jt < NJT; ++jt) {
        const int s = jt & 1;
        if (s == 0) { MBARRIER_WAIT_PARITY(mb0, ph0); ph0 ^= 1; }
        else        { MBARRIER_WAIT_PARITY(mb1, ph1); ph1 ^= 1; }

        const uint32_t sBh = sb + SB0 + s * 65536;
        const uint32_t sBl = sBh + 32768;

        float acc[2][4][4];
#pragma unroll
        for (int mt = 0; mt < 2; ++mt)
#pragma unroll
            for (int n8 = 0; n8 < 4; ++n8)
#pragma unroll
                for (int v = 0; v < 4; ++v) acc[mt][n8][v] = 0.f;

        // register-pipelined fragment loop: load ks+1 before MMAs of ks
        Frag f[2];
        load_frag(f[0], sAh, sAl, sBh, sBl, a_r, a_cb, b_n, b_cb, 0);
#pragma unroll
        for (int ks = 0; ks < 8; ++ks) {
            if (ks + 1 < 8)
                load_frag(f[(ks + 1) & 1], sAh, sAl, sBh, sBl, a_r, a_cb, b_n, b_cb, ks + 1);
            mma_frag(acc, f[ks & 1]);
        }
        __syncthreads();   // all warps done reading stage s -> safe to refill

        if (jt + 2 < NJT && tid == 0) {
            uint32_t mb = (s == 0) ? mb0 : mb1;
            MBARRIER_EXPECT_TX(mb, 65536);
            bulk32k(sBh, khb + (size_t)(jt + 2) * 32768, mb);
            bulk32k(sBl, klb + (size_t)(jt + 2) * 32768, mb);
        }

        // epilogue: relu(sim/64)^2, unnormalized
#pragma unroll
        for (int mt = 0; mt < 2; ++mt) {
#pragma unroll
            for (int n8 = 0; n8 < 4; ++n8) {
                int grow = wm0 + mt * 16 + (lane >> 2);
                int gcol = jt * 128 + wn0 + n8 * 8 + (lane & 3) * 2;
                float* p0 = out + (brow + grow) * SEQ + gcol;
                float* p1 = p0 + (size_t)8 * SEQ;
                float s0, s1;
                float2 v0, v1;
                s0 = fmaxf(acc[mt][n8][0] * 0.015625f, 0.f); v0.x = s0 * s0;
                s1 = fmaxf(acc[mt][n8][1] * 0.015625f, 0.f); v0.y = s1 * s1;
                s0 = fmaxf(acc[mt][n8][2] * 0.015625f, 0.f); v1.x = s0 * s0;
                s1 = fmaxf(acc[mt][n8][3] * 0.015625f, 0.f); v1.y = s1 * s1;
                *(float2*)p0 = v0;
                *(float2*)p1 = v1;
            }
        }
    }
}

// ---------------------------------------------------------------------------
// Kernel 3: per-row sum + in-place rescale.
// ---------------------------------------------------------------------------
__global__ __launch_bounds__(256) void norm_kernel(float* __restrict__ out)
{
    const size_t row = blockIdx.x;
    float4* p = (float4*)(out + row * SEQ);
    const int tid = threadIdx.x;

    float4 v[4];
    float s = 0.f;
#pragma unroll
    for (int i = 0; i < 4; ++i) {
        v[i] = p[tid + 256 * i];
        s += v[i].x + v[i].y + v[i].z + v[i].w;
    }

    __shared__ float red[256];
    red[tid] = s;
    __syncthreads();
#pragma unroll
    for (int o = 128; o > 0; o >>= 1) {
        if (tid < o) red[tid] += red[tid + o];
        __syncthreads();
    }
    float inv = 1.f / (red[0] + 1e-6f);

#pragma unroll
    for (int i = 0; i < 4; ++i) {
        v[i].x *= inv; v[i].y *= inv; v[i].z *= inv; v[i].w *= inv;
        p[tid + 256 * i] = v[i];
    }
}

// ---------------------------------------------------------------------------
extern "C" void kernel_launch(void* const* d_in, const int* in_sizes, int n_in,
                              void* d_out, int out_size)
{
    const float* x     = (const float*)d_in[0];
    const float* ln_w  = (const float*)d_in[1];
    const float* ln_b  = (const float*)d_in[2];
    const float* w_qk  = (const float*)d_in[3];
    const float* b_qk  = (const float*)d_in[4];
    const float* gamma = (const float*)d_in[5];
    const float* beta  = (const float*)d_in[6];
    float* out = (float*)d_out;

    wsplit_kernel<<<QK, 128>>>(w_qk, ln_w, ln_b);
    xsplit_kernel<<<(BATCH * SEQ) / 8, 256>>>(x);

    cudaFuncSetAttribute(qk_kernel, cudaFuncAttributeMaxDynamicSharedMemorySize, QK_SMEM);
    qk_kernel<<<(BATCH * SEQ) / 64, 256, QK_SMEM>>>(b_qk, gamma, beta);

    cudaFuncSetAttribute(attn_kernel, cudaFuncAttributeMaxDynamicSharedMemorySize, ATT_SMEM);
    dim3 g2(SEQ / 128, BATCH);
    attn_kernel<<<g2, 512, ATT_SMEM>>>(out);

    norm_kernel<<<BATCH * SEQ, 256>>>(out);
}

// round 14
// speedup vs baseline: 1.0299x; 1.0299x over previous
#include <cuda_runtime.h>
#include <cuda_bf16.h>
#include <cstdint>
#include <math.h>

#define BATCH 4
#define SEQ 4096
#define DIM 512
#define QK 128
#define LN_EPS 1e-5f
#define NJT 32

// scratch (allocation-free rule: __device__ globals)
__device__ __nv_bfloat16 g_qh[BATCH * SEQ * QK];
__device__ __nv_bfloat16 g_ql[BATCH * SEQ * QK];
__device__ __nv_bfloat16 g_kh[BATCH * SEQ * QK];
__device__ __nv_bfloat16 g_kl[BATCH * SEQ * QK];
__device__ __nv_bfloat16 g_wh[QK * DIM];     // (lnw ⊙ W) hi
__device__ __nv_bfloat16 g_wl[QK * DIM];     // (lnw ⊙ W) lo
__device__ __nv_bfloat16 g_xh[BATCH * SEQ * DIM];
__device__ __nv_bfloat16 g_xl[BATCH * SEQ * DIM];
__device__ float g_mu[BATCH * SEQ];
__device__ float g_rs[BATCH * SEQ];
__device__ float g_c1[QK];
__device__ float g_c2[QK];

// ---------------------------------------------------------------------------
// common helpers
// ---------------------------------------------------------------------------
__device__ __forceinline__ uint32_t smem_u32(const void* p) {
    uint32_t a;
    asm("{ .reg .u64 t; cvta.to.shared.u64 t, %1; cvt.u32.u64 %0, t; }" : "=r"(a) : "l"(p));
    return a;
}
__device__ __forceinline__ void cpasync16(uint32_t dst, const void* src) {
    asm volatile("cp.async.cg.shared.global [%0], [%1], 16;"
                 :: "r"(dst), "l"(__cvta_generic_to_global(src)));
}
__device__ __forceinline__ void ldsm4(uint32_t a, uint32_t& r0, uint32_t& r1,
                                      uint32_t& r2, uint32_t& r3) {
    asm volatile("ldmatrix.sync.aligned.m8n8.x4.shared.b16 {%0,%1,%2,%3}, [%4];"
                 : "=r"(r0), "=r"(r1), "=r"(r2), "=r"(r3) : "r"(a));
}
__device__ __forceinline__ void mma16816(float* c,
                                         const uint32_t* a, uint32_t b0, uint32_t b1) {
    asm volatile("mma.sync.aligned.m16n8k16.row.col.f32.bf16.bf16.f32 "
                 "{%0,%1,%2,%3}, {%4,%5,%6,%7}, {%8,%9}, {%0,%1,%2,%3};"
                 : "+f"(c[0]), "+f"(c[1]), "+f"(c[2]), "+f"(c[3])
                 : "r"(a[0]), "r"(a[1]), "r"(a[2]), "r"(a[3]), "r"(b0), "r"(b1));
}
// swizzled offset: row stride 256B (128 bf16), 16 chunks of 16B, chunk ^= row&7
__device__ __forceinline__ uint32_t swoff(int r, int ch) {
    return (uint32_t)r * 256u + (uint32_t)((ch ^ (r & 7)) << 4);
}

// ---------------------------------------------------------------------------
// Kernel 0 (merged): blocks [0,2048): x hi/lo split + LN stats (8 rows/block);
//                    blocks [2048,2176): W fold/split + c1/c2 (1 out-ch/block).
// ---------------------------------------------------------------------------
__global__ __launch_bounds__(256) void split_kernel(
    const float* __restrict__ x, const float* __restrict__ w,
    const float* __restrict__ lnw, const float* __restrict__ lnb)
{
    const int tid = threadIdx.x, wid = tid >> 5, lane = tid & 31;

    if (blockIdx.x >= 2048) {
        // ---- W part: one output channel per (block-2048), 128 active threads ----
        if (tid >= 128) return;
        const int e = blockIdx.x - 2048;
        float4 v  = ((const float4*)(w + (size_t)e * DIM))[tid];
        float4 lw = ((const float4*)lnw)[tid];
        float4 lb = ((const float4*)lnb)[tid];
        float sv[4] = { v.x * lw.x, v.y * lw.y, v.z * lw.z, v.w * lw.w };
        float s1 = sv[0] + sv[1] + sv[2] + sv[3];
        float s2 = v.x * lb.x + v.y * lb.y + v.z * lb.z + v.w * lb.w;

        __nv_bfloat16 h4[4], l4[4];
#pragma unroll
        for (int j = 0; j < 4; ++j) {
            h4[j] = __float2bfloat16(sv[j]);
            l4[j] = __float2bfloat16(sv[j] - __bfloat162float(h4[j]));
        }
        *(uint2*)(g_wh + (size_t)e * DIM + tid * 4) = *(uint2*)h4;
        *(uint2*)(g_wl + (size_t)e * DIM + tid * 4) = *(uint2*)l4;

#pragma unroll
        for (int o = 16; o > 0; o >>= 1) {
            s1 += __shfl_xor_sync(0xFFFFFFFFu, s1, o);
            s2 += __shfl_xor_sync(0xFFFFFFFFu, s2, o);
        }
        __shared__ float r1[4], r2[4];
        if (lane == 0) { r1[wid] = s1; r2[wid] = s2; }
        __syncthreads();
        if (tid == 0) {
            g_c1[e] = r1[0] + r1[1] + r1[2] + r1[3];
            g_c2[e] = r2[0] + r2[1] + r2[2] + r2[3];
        }
        return;
    }

    // ---- x part: one warp per row, 8 rows per block ----
    const size_t row = (size_t)blockIdx.x * 8 + wid;
    const float4* xr = (const float4*)(x + row * DIM);

    float4 v[4];
    float s = 0.f, sq = 0.f;
#pragma unroll
    for (int i = 0; i < 4; ++i) {
        v[i] = xr[lane + 32 * i];
        s  += v[i].x + v[i].y + v[i].z + v[i].w;
        sq += v[i].x * v[i].x + v[i].y * v[i].y + v[i].z * v[i].z + v[i].w * v[i].w;
    }
#pragma unroll
    for (int o = 16; o > 0; o >>= 1) {
        s  += __shfl_xor_sync(0xFFFFFFFFu, s,  o);
        sq += __shfl_xor_sync(0xFFFFFFFFu, sq, o);
    }
    if (lane == 0) {
        float mu  = s * (1.f / DIM);
        float var = sq * (1.f / DIM) - mu * mu;
        g_mu[row] = mu;
        g_rs[row] = rsqrtf(var + LN_EPS);
    }
#pragma unroll
    for (int i = 0; i < 4; ++i) {
        float vv[4] = { v[i].x, v[i].y, v[i].z, v[i].w };
        __nv_bfloat16 h4[4], l4[4];
#pragma unroll
        for (int j = 0; j < 4; ++j) {
            h4[j] = __float2bfloat16(vv[j]);
            l4[j] = __float2bfloat16(vv[j] - __bfloat162float(h4[j]));
        }
        size_t off = row * DIM + (size_t)(lane + 32 * i) * 4;
        *(uint2*)(g_xh + off) = *(uint2*)h4;
        *(uint2*)(g_xl + off) = *(uint2*)l4;
    }
}

// ---------------------------------------------------------------------------
// Kernel 1: pure-GEMM qk (R10 configuration, linear q/k output layout).
// ---------------------------------------------------------------------------
#define QSA0 0
#define QSW0 65536
#define QK_SMEM 196608

__global__ __launch_bounds__(256, 1) void qk_kernel(
    const float* __restrict__ bq,
    const float* __restrict__ gamma, const float* __restrict__ beta)
{
    extern __shared__ char sm[];
    const uint32_t sb = smem_u32(sm);
    const int tid = threadIdx.x, wid = tid >> 5, lane = tid & 31;
    const int row0 = blockIdx.x * 64;

#pragma unroll
    for (int s = 0; s < 2; ++s) {
#pragma unroll
        for (int i = 0; i < 4; ++i) {
            int idx = tid + 256 * i;
            int r = idx >> 4, ch = idx & 15;
            cpasync16(sb + QSA0 + s * 32768 + swoff(r, ch),
                      g_xh + (size_t)(row0 + r) * DIM + s * 128 + ch * 8);
            cpasync16(sb + QSA0 + s * 32768 + 16384 + swoff(r, ch),
                      g_xl + (size_t)(row0 + r) * DIM + s * 128 + ch * 8);
        }
#pragma unroll
        for (int i = 0; i < 8; ++i) {
            int idx = tid + 256 * i;
            int r = idx >> 4, ch = idx & 15;
            cpasync16(sb + QSW0 + s * 65536 + swoff(r, ch),
                      g_wh + (size_t)r * DIM + s * 128 + ch * 8);
            cpasync16(sb + QSW0 + s * 65536 + 32768 + swoff(r, ch),
                      g_wl + (size_t)r * DIM + s * 128 + ch * 8);
        }
        asm volatile("cp.async.commit_group;" ::: "memory");
    }

    const int wm0 = (wid & 1) * 32;
    const int wn0 = (wid >> 1) * 32;
    const int a_r  = wm0 + (lane & 15);
    const int a_cb = lane >> 4;
    const int b_n  = wn0 + (lane & 7) + ((lane & 16) >> 1);
    const int b_cb = (lane >> 3) & 1;

    float acc[2][4][4];
#pragma unroll
    for (int mt = 0; mt < 2; ++mt)
#pragma unroll
        for (int n8 = 0; n8 < 4; ++n8)
#pragma unroll
            for (int v = 0; v < 4; ++v) acc[mt][n8][v] = 0.f;

#pragma unroll 1
    for (int c = 0; c < 4; ++c) {
        const int s = c & 1;
        asm volatile("cp.async.wait_group 1;" ::: "memory");
        __syncthreads();

        const uint32_t sAh = sb + QSA0 + s * 32768;
        const uint32_t sAl = sAh + 16384;
        const uint32_t sWh = sb + QSW0 + s * 65536;
        const uint32_t sWl = sWh + 32768;

#pragma unroll
        for (int ks = 0; ks < 8; ++ks) {
            uint32_t ah[2][4], al[2][4];
#pragma unroll
            for (int mt = 0; mt < 2; ++mt) {
                int r = a_r + mt * 16;
                ldsm4(sAh + swoff(r, ks * 2 + a_cb), ah[mt][0], ah[mt][1], ah[mt][2], ah[mt][3]);
                ldsm4(sAl + swoff(r, ks * 2 + a_cb), al[mt][0], al[mt][1], al[mt][2], al[mt][3]);
            }
            uint32_t bh[2][4], bl[2][4];
#pragma unroll
            for (int nb = 0; nb < 2; ++nb) {
                int n = b_n + nb * 16;
                ldsm4(sWh + swoff(n, ks * 2 + b_cb), bh[nb][0], bh[nb][1], bh[nb][2], bh[nb][3]);
                ldsm4(sWl + swoff(n, ks * 2 + b_cb), bl[nb][0], bl[nb][1], bl[nb][2], bl[nb][3]);
            }
#pragma unroll
            for (int mt = 0; mt < 2; ++mt)
#pragma unroll
                for (int n8 = 0; n8 < 4; ++n8) {
                    const int nb = n8 >> 1, hf = (n8 & 1) * 2;
                    mma16816(acc[mt][n8], ah[mt], bh[nb][hf], bh[nb][hf + 1]);
                    mma16816(acc[mt][n8], ah[mt], bl[nb][hf], bl[nb][hf + 1]);
                    mma16816(acc[mt][n8], al[mt], bh[nb][hf], bh[nb][hf + 1]);
                }
        }
        __syncthreads();

        if (c + 2 < 4) {
#pragma unroll
            for (int i = 0; i < 4; ++i) {
                int idx = tid + 256 * i;
                int r = idx >> 4, ch = idx & 15;
                cpasync16(sAh + swoff(r, ch),
                          g_xh + (size_t)(row0 + r) * DIM + (c + 2) * 128 + ch * 8);
                cpasync16(sAl + swoff(r, ch),
                          g_xl + (size_t)(row0 + r) * DIM + (c + 2) * 128 + ch * 8);
            }
#pragma unroll
            for (int i = 0; i < 8; ++i) {
                int idx = tid + 256 * i;
                int r = idx >> 4, ch = idx & 15;
                cpasync16(sWh + swoff(r, ch), g_wh + (size_t)r * DIM + (c + 2) * 128 + ch * 8);
                cpasync16(sWl + swoff(r, ch), g_wl + (size_t)r * DIM + (c + 2) * 128 + ch * 8);
            }
        }
        asm volatile("cp.async.commit_group;" ::: "memory");
    }

    float rsv[2][2], muv[2][2];
#pragma unroll
    for (int mt = 0; mt < 2; ++mt)
#pragma unroll
        for (int half = 0; half < 2; ++half) {
            int row = row0 + wm0 + mt * 16 + (lane >> 2) + half * 8;
            rsv[mt][half] = g_rs[row];
            muv[mt][half] = g_mu[row];
        }

#pragma unroll
    for (int n8 = 0; n8 < 4; ++n8) {
        int e0 = wn0 + n8 * 8 + (lane & 3) * 2;
        float c10 = g_c1[e0],          c11 = g_c1[e0 + 1];
        float c20 = g_c2[e0],          c21 = g_c2[e0 + 1];
        float bb0 = bq[e0],            bb1 = bq[e0 + 1];
        float g00 = gamma[e0],         g01 = gamma[e0 + 1];
        float b00 = beta[e0],          b01 = beta[e0 + 1];
        float g10 = gamma[QK + e0],    g11 = gamma[QK + e0 + 1];
        float b10 = beta[QK + e0],     b11 = beta[QK + e0 + 1];
#pragma unroll
        for (int mt = 0; mt < 2; ++mt) {
#pragma unroll
            for (int half = 0; half < 2; ++half) {
                int row = row0 + wm0 + mt * 16 + (lane >> 2) + half * 8;
                float rs = rsv[mt][half], mu = muv[mt][half];
                float z0 = rs * (acc[mt][n8][half * 2]     - mu * c10) + c20 + bb0;
                float z1 = rs * (acc[mt][n8][half * 2 + 1] - mu * c11) + c21 + bb1;
                float v0 = z0 / (1.f + expf(-z0));
                float v1 = z1 / (1.f + expf(-z1));
                float q0 = v0 * g00 + b00, q1 = v1 * g01 + b01;
                float k0 = v0 * g10 + b10, k1 = v1 * g11 + b11;
                __nv_bfloat16 t0, t1;
                size_t off = (size_t)row * QK + e0;
                t0 = __float2bfloat16(q0); t1 = __float2bfloat16(q1);
                *(uint32_t*)(g_qh + off) = (uint32_t)__bfloat16_as_ushort(t0) |
                                           ((uint32_t)__bfloat16_as_ushort(t1) << 16);
                __nv_bfloat16 r0 = __float2bfloat16(q0 - __bfloat162float(t0));
                __nv_bfloat16 r1 = __float2bfloat16(q1 - __bfloat162float(t1));
                *(uint32_t*)(g_ql + off) = (uint32_t)__bfloat16_as_ushort(r0) |
                                           ((uint32_t)__bfloat16_as_ushort(r1) << 16);
                t0 = __float2bfloat16(k0); t1 = __float2bfloat16(k1);
                *(uint32_t*)(g_kh + off) = (uint32_t)__bfloat16_as_ushort(t0) |
                                           ((uint32_t)__bfloat16_as_ushort(t1) << 16);
                r0 = __float2bfloat16(k0 - __bfloat162float(t0));
                r1 = __float2bfloat16(k1 - __bfloat162float(t1));
                *(uint32_t*)(g_kl + off) = (uint32_t)__bfloat16_as_ushort(r0) |
                                           ((uint32_t)__bfloat16_as_ushort(r1) << 16);
            }
        }
    }
}

// ---------------------------------------------------------------------------
// Kernel 2: strip-persistent HMMA sim GEMM (R10 configuration, 512 threads).
// ---------------------------------------------------------------------------
#define SA_HI 0
#define SA_LO 32768
#define SB0   65536
#define ATT_SMEM 196608

__device__ __forceinline__ void load_tile128_512(uint32_t dst, const __nv_bfloat16* g, int tid) {
#pragma unroll
    for (int i = 0; i < 4; ++i) {
        int idx = tid + 512 * i;
        int r = idx >> 4, ch = idx & 15;
        cpasync16(dst + swoff(r, ch), g + (size_t)r * QK + ch * 8);
    }
}

__global__ __launch_bounds__(512, 1) void attn_kernel(float* __restrict__ out)
{
    extern __shared__ char smem[];
    const uint32_t sb = smem_u32(smem);
    const int tid = threadIdx.x, wid = tid >> 5, lane = tid & 31;
    const int b = blockIdx.y, strip = blockIdx.x;
    const size_t brow = (size_t)b * SEQ + strip * 128;

    const __nv_bfloat16* qh = g_qh + brow * QK;
    const __nv_bfloat16* ql = g_ql + brow * QK;
    const __nv_bfloat16* khb = g_kh + (size_t)b * SEQ * QK;
    const __nv_bfloat16* klb = g_kl + (size_t)b * SEQ * QK;

    load_tile128_512(sb + SA_HI, qh, tid);
    load_tile128_512(sb + SA_LO, ql, tid);
    load_tile128_512(sb + SB0,         khb, tid);
    load_tile128_512(sb + SB0 + 32768, klb, tid);
    asm volatile("cp.async.commit_group;" ::: "memory");
    load_tile128_512(sb + SB0 + 65536,         khb + (size_t)128 * QK, tid);
    load_tile128_512(sb + SB0 + 65536 + 32768, klb + (size_t)128 * QK, tid);
    asm volatile("cp.async.commit_group;" ::: "memory");

    // 16 warps: 4(m) x 4(n); warp tile 32m x 32n
    const int wm0 = (wid & 3) * 32;
    const int wn0 = (wid >> 2) * 32;
    const int a_r  = wm0 + (lane & 15);
    const int a_cb = lane >> 4;
    const int b_n  = wn0 + (lane & 7) + ((lane & 16) >> 1);
    const int b_cb = (lane >> 3) & 1;

    for (int jt = 0; jt < NJT; ++jt) {
        const int s = jt & 1;
        asm volatile("cp.async.wait_group 1;" ::: "memory");
        __syncthreads();

        const uint32_t sBh = sb + SB0 + s * 65536;
        const uint32_t sBl = sBh + 32768;

        float acc[2][4][4];
#pragma unroll
        for (int mt = 0; mt < 2; ++mt)
#pragma unroll
            for (int n8 = 0; n8 < 4; ++n8)
#pragma unroll
                for (int v = 0; v < 4; ++v) acc[mt][n8][v] = 0.f;

#pragma unroll
        for (int ks = 0; ks < 8; ++ks) {
            uint32_t ah[2][4], al[2][4];
#pragma unroll
            for (int mt = 0; mt < 2; ++mt) {
                int r = a_r + mt * 16;
                ldsm4(sb + SA_HI + swoff(r, ks * 2 + a_cb), ah[mt][0], ah[mt][1], ah[mt][2], ah[mt][3]);
                ldsm4(sb + SA_LO + swoff(r, ks * 2 + a_cb), al[mt][0], al[mt][1], al[mt][2], al[mt][3]);
            }
            uint32_t bh[2][4], bl[2][4];
#pragma unroll
            for (int nb = 0; nb < 2; ++nb) {
                int n = b_n + nb * 16;
                ldsm4(sBh + swoff(n, ks * 2 + b_cb), bh[nb][0], bh[nb][1], bh[nb][2], bh[nb][3]);
                ldsm4(sBl + swoff(n, ks * 2 + b_cb), bl[nb][0], bl[nb][1], bl[nb][2], bl[nb][3]);
            }
#pragma unroll
            for (int mt = 0; mt < 2; ++mt)
#pragma unroll
                for (int n8 = 0; n8 < 4; ++n8) {
                    const int nb = n8 >> 1, hf = (n8 & 1) * 2;
                    mma16816(acc[mt][n8], ah[mt], bh[nb][hf], bh[nb][hf + 1]);
                    mma16816(acc[mt][n8], ah[mt], bl[nb][hf], bl[nb][hf + 1]);
                    mma16816(acc[mt][n8], al[mt], bh[nb][hf], bh[nb][hf + 1]);
                }
        }
        __syncthreads();

        if (jt + 2 < NJT) {
            load_tile128_512(sBh, khb + (size_t)(jt + 2) * 128 * QK, tid);
            load_tile128_512(sBl, klb + (size_t)(jt + 2) * 128 * QK, tid);
        }
        asm volatile("cp.async.commit_group;" ::: "memory");

        // epilogue: relu(sim/64)^2, unnormalized
#pragma unroll
        for (int mt = 0; mt < 2; ++mt) {
#pragma unroll
            for (int n8 = 0; n8 < 4; ++n8) {
                int grow = wm0 + mt * 16 + (lane >> 2);
                int gcol = jt * 128 + wn0 + n8 * 8 + (lane & 3) * 2;
                float* p0 = out + (brow + grow) * SEQ + gcol;
                float* p1 = p0 + (size_t)8 * SEQ;
                float s0, s1;
                float2 v0, v1;
                s0 = fmaxf(acc[mt][n8][0] * 0.015625f, 0.f); v0.x = s0 * s0;
                s1 = fmaxf(acc[mt][n8][1] * 0.015625f, 0.f); v0.y = s1 * s1;
                s0 = fmaxf(acc[mt][n8][2] * 0.015625f, 0.f); v1.x = s0 * s0;
                s1 = fmaxf(acc[mt][n8][3] * 0.015625f, 0.f); v1.y = s1 * s1;
                *(float2*)p0 = v0;
                *(float2*)p1 = v1;
            }
        }
    }
}

// ---------------------------------------------------------------------------
// Kernel 3: per-row sum + in-place rescale.
// ---------------------------------------------------------------------------
__global__ __launch_bounds__(256) void norm_kernel(float* __restrict__ out)
{
    const size_t row = blockIdx.x;
    float4* p = (float4*)(out + row * SEQ);
    const int tid = threadIdx.x;

    float4 v[4];
    float s = 0.f;
#pragma unroll
    for (int i = 0; i < 4; ++i) {
        v[i] = p[tid + 256 * i];
        s += v[i].x + v[i].y + v[i].z + v[i].w;
    }

    __shared__ float red[256];
    red[tid] = s;
    __syncthreads();
#pragma unroll
    for (int o = 128; o > 0; o >>= 1) {
        if (tid < o) red[tid] += red[tid + o];
        __syncthreads();
    }
    float inv = 1.f / (red[0] + 1e-6f);

#pragma unroll
    for (int i = 0; i < 4; ++i) {
        v[i].x *= inv; v[i].y *= inv; v[i].z *= inv; v[i].w *= inv;
        p[tid + 256 * i] = v[i];
    }
}

// ---------------------------------------------------------------------------
extern "C" void kernel_launch(void* const* d_in, const int* in_sizes, int n_in,
                              void* d_out, int out_size)
{
    const float* x     = (const float*)d_in[0];
    const float* ln_w  = (const float*)d_in[1];
    const float* ln_b  = (const float*)d_in[2];
    const float* w_qk  = (const float*)d_in[3];
    const float* b_qk  = (const float*)d_in[4];
    const float* gamma = (const float*)d_in[5];
    const float* beta  = (const float*)d_in[6];
    float* out = (float*)d_out;

    split_kernel<<<2048 + 128, 256>>>(x, w_qk, ln_w, ln_b);

    cudaFuncSetAttribute(qk_kernel, cudaFuncAttributeMaxDynamicSharedMemorySize, QK_SMEM);
    qk_kernel<<<(BATCH * SEQ) / 64, 256, QK_SMEM>>>(b_qk, gamma, beta);

    cudaFuncSetAttribute(attn_kernel, cudaFuncAttributeMaxDynamicSharedMemorySize, ATT_SMEM);
    dim3 g2(SEQ / 128, BATCH);
    attn_kernel<<<g2, 512, ATT_SMEM>>>(out);

    norm_kernel<<<BATCH * SEQ, 256>>>(out);
}

// round 15
// speedup vs baseline: 1.0787x; 1.0473x over previous
#include <cuda_runtime.h>
#include <cuda_bf16.h>
#include <cuda_fp16.h>
#include <cstdint>
#include <math.h>

#define BATCH 4
#define SEQ 4096
#define DIM 512
#define QK 128
#define LN_EPS 1e-5f
#define NJT 32

// scratch (allocation-free rule: __device__ globals)
__device__ __nv_bfloat16 g_qh[BATCH * SEQ * QK];
__device__ __nv_bfloat16 g_ql[BATCH * SEQ * QK];
__device__ __nv_bfloat16 g_kh[BATCH * SEQ * QK];
__device__ __nv_bfloat16 g_kl[BATCH * SEQ * QK];
__device__ __nv_bfloat16 g_wh[QK * DIM];     // (lnw ⊙ W) hi
__device__ __nv_bfloat16 g_wl[QK * DIM];     // (lnw ⊙ W) lo
__device__ __nv_bfloat16 g_xh[BATCH * SEQ * DIM];
__device__ __nv_bfloat16 g_xl[BATCH * SEQ * DIM];
__device__ float g_mu[BATCH * SEQ];
__device__ float g_rs[BATCH * SEQ];
__device__ float g_c1[QK];
__device__ float g_c2[QK];
__device__ __half g_s[(size_t)BATCH * SEQ * SEQ];   // raw q·k, fp16 (134MB)

// ---------------------------------------------------------------------------
// common helpers
// ---------------------------------------------------------------------------
__device__ __forceinline__ uint32_t smem_u32(const void* p) {
    uint32_t a;
    asm("{ .reg .u64 t; cvta.to.shared.u64 t, %1; cvt.u32.u64 %0, t; }" : "=r"(a) : "l"(p));
    return a;
}
__device__ __forceinline__ void cpasync16(uint32_t dst, const void* src) {
    asm volatile("cp.async.cg.shared.global [%0], [%1], 16;"
                 :: "r"(dst), "l"(__cvta_generic_to_global(src)));
}
__device__ __forceinline__ void ldsm4(uint32_t a, uint32_t& r0, uint32_t& r1,
                                      uint32_t& r2, uint32_t& r3) {
    asm volatile("ldmatrix.sync.aligned.m8n8.x4.shared.b16 {%0,%1,%2,%3}, [%4];"
                 : "=r"(r0), "=r"(r1), "=r"(r2), "=r"(r3) : "r"(a));
}
__device__ __forceinline__ void mma16816(float* c,
                                         const uint32_t* a, uint32_t b0, uint32_t b1) {
    asm volatile("mma.sync.aligned.m16n8k16.row.col.f32.bf16.bf16.f32 "
                 "{%0,%1,%2,%3}, {%4,%5,%6,%7}, {%8,%9}, {%0,%1,%2,%3};"
                 : "+f"(c[0]), "+f"(c[1]), "+f"(c[2]), "+f"(c[3])
                 : "r"(a[0]), "r"(a[1]), "r"(a[2]), "r"(a[3]), "r"(b0), "r"(b1));
}
// swizzled offset: row stride 256B (128 bf16), 16 chunks of 16B, chunk ^= row&7
__device__ __forceinline__ uint32_t swoff(int r, int ch) {
    return (uint32_t)r * 256u + (uint32_t)((ch ^ (r & 7)) << 4);
}

// ---------------------------------------------------------------------------
// Kernel 0 (merged): blocks [0,2048): x hi/lo split + LN stats (8 rows/block);
//                    blocks [2048,2176): W fold/split + c1/c2 (1 out-ch/block).
// ---------------------------------------------------------------------------
__global__ __launch_bounds__(256) void split_kernel(
    const float* __restrict__ x, const float* __restrict__ w,
    const float* __restrict__ lnw, const float* __restrict__ lnb)
{
    const int tid = threadIdx.x, wid = tid >> 5, lane = tid & 31;

    if (blockIdx.x >= 2048) {
        if (tid >= 128) return;
        const int e = blockIdx.x - 2048;
        float4 v  = ((const float4*)(w + (size_t)e * DIM))[tid];
        float4 lw = ((const float4*)lnw)[tid];
        float4 lb = ((const float4*)lnb)[tid];
        float sv[4] = { v.x * lw.x, v.y * lw.y, v.z * lw.z, v.w * lw.w };
        float s1 = sv[0] + sv[1] + sv[2] + sv[3];
        float s2 = v.x * lb.x + v.y * lb.y + v.z * lb.z + v.w * lb.w;

        __nv_bfloat16 h4[4], l4[4];
#pragma unroll
        for (int j = 0; j < 4; ++j) {
            h4[j] = __float2bfloat16(sv[j]);
            l4[j] = __float2bfloat16(sv[j] - __bfloat162float(h4[j]));
        }
        *(uint2*)(g_wh + (size_t)e * DIM + tid * 4) = *(uint2*)h4;
        *(uint2*)(g_wl + (size_t)e * DIM + tid * 4) = *(uint2*)l4;

#pragma unroll
        for (int o = 16; o > 0; o >>= 1) {
            s1 += __shfl_xor_sync(0xFFFFFFFFu, s1, o);
            s2 += __shfl_xor_sync(0xFFFFFFFFu, s2, o);
        }
        __shared__ float r1[4], r2[4];
        if (lane == 0) { r1[wid] = s1; r2[wid] = s2; }
        __syncthreads();
        if (tid == 0) {
            g_c1[e] = r1[0] + r1[1] + r1[2] + r1[3];
            g_c2[e] = r2[0] + r2[1] + r2[2] + r2[3];
        }
        return;
    }

    const size_t row = (size_t)blockIdx.x * 8 + wid;
    const float4* xr = (const float4*)(x + row * DIM);

    float4 v[4];
    float s = 0.f, sq = 0.f;
#pragma unroll
    for (int i = 0; i < 4; ++i) {
        v[i] = xr[lane + 32 * i];
        s  += v[i].x + v[i].y + v[i].z + v[i].w;
        sq += v[i].x * v[i].x + v[i].y * v[i].y + v[i].z * v[i].z + v[i].w * v[i].w;
    }
#pragma unroll
    for (int o = 16; o > 0; o >>= 1) {
        s  += __shfl_xor_sync(0xFFFFFFFFu, s,  o);
        sq += __shfl_xor_sync(0xFFFFFFFFu, sq, o);
    }
    if (lane == 0) {
        float mu  = s * (1.f / DIM);
        float var = sq * (1.f / DIM) - mu * mu;
        g_mu[row] = mu;
        g_rs[row] = rsqrtf(var + LN_EPS);
    }
#pragma unroll
    for (int i = 0; i < 4; ++i) {
        float vv[4] = { v[i].x, v[i].y, v[i].z, v[i].w };
        __nv_bfloat16 h4[4], l4[4];
#pragma unroll
        for (int j = 0; j < 4; ++j) {
            h4[j] = __float2bfloat16(vv[j]);
            l4[j] = __float2bfloat16(vv[j] - __bfloat162float(h4[j]));
        }
        size_t off = row * DIM + (size_t)(lane + 32 * i) * 4;
        *(uint2*)(g_xh + off) = *(uint2*)h4;
        *(uint2*)(g_xl + off) = *(uint2*)l4;
    }
}

// ---------------------------------------------------------------------------
// Kernel 1: pure-GEMM qk (R10/R14 configuration).
// ---------------------------------------------------------------------------
#define QSA0 0
#define QSW0 65536
#define QK_SMEM 196608

__global__ __launch_bounds__(256, 1) void qk_kernel(
    const float* __restrict__ bq,
    const float* __restrict__ gamma, const float* __restrict__ beta)
{
    extern __shared__ char sm[];
    const uint32_t sb = smem_u32(sm);
    const int tid = threadIdx.x, wid = tid >> 5, lane = tid & 31;
    const int row0 = blockIdx.x * 64;

#pragma unroll
    for (int s = 0; s < 2; ++s) {
#pragma unroll
        for (int i = 0; i < 4; ++i) {
            int idx = tid + 256 * i;
            int r = idx >> 4, ch = idx & 15;
            cpasync16(sb + QSA0 + s * 32768 + swoff(r, ch),
                      g_xh + (size_t)(row0 + r) * DIM + s * 128 + ch * 8);
            cpasync16(sb + QSA0 + s * 32768 + 16384 + swoff(r, ch),
                      g_xl + (size_t)(row0 + r) * DIM + s * 128 + ch * 8);
        }
#pragma unroll
        for (int i = 0; i < 8; ++i) {
            int idx = tid + 256 * i;
            int r = idx >> 4, ch = idx & 15;
            cpasync16(sb + QSW0 + s * 65536 + swoff(r, ch),
                      g_wh + (size_t)r * DIM + s * 128 + ch * 8);
            cpasync16(sb + QSW0 + s * 65536 + 32768 + swoff(r, ch),
                      g_wl + (size_t)r * DIM + s * 128 + ch * 8);
        }
        asm volatile("cp.async.commit_group;" ::: "memory");
    }

    const int wm0 = (wid & 1) * 32;
    const int wn0 = (wid >> 1) * 32;
    const int a_r  = wm0 + (lane & 15);
    const int a_cb = lane >> 4;
    const int b_n  = wn0 + (lane & 7) + ((lane & 16) >> 1);
    const int b_cb = (lane >> 3) & 1;

    float acc[2][4][4];
#pragma unroll
    for (int mt = 0; mt < 2; ++mt)
#pragma unroll
        for (int n8 = 0; n8 < 4; ++n8)
#pragma unroll
            for (int v = 0; v < 4; ++v) acc[mt][n8][v] = 0.f;

#pragma unroll 1
    for (int c = 0; c < 4; ++c) {
        const int s = c & 1;
        asm volatile("cp.async.wait_group 1;" ::: "memory");
        __syncthreads();

        const uint32_t sAh = sb + QSA0 + s * 32768;
        const uint32_t sAl = sAh + 16384;
        const uint32_t sWh = sb + QSW0 + s * 65536;
        const uint32_t sWl = sWh + 32768;

#pragma unroll
        for (int ks = 0; ks < 8; ++ks) {
            uint32_t ah[2][4], al[2][4];
#pragma unroll
            for (int mt = 0; mt < 2; ++mt) {
                int r = a_r + mt * 16;
                ldsm4(sAh + swoff(r, ks * 2 + a_cb), ah[mt][0], ah[mt][1], ah[mt][2], ah[mt][3]);
                ldsm4(sAl + swoff(r, ks * 2 + a_cb), al[mt][0], al[mt][1], al[mt][2], al[mt][3]);
            }
            uint32_t bh[2][4], bl[2][4];
#pragma unroll
            for (int nb = 0; nb < 2; ++nb) {
                int n = b_n + nb * 16;
                ldsm4(sWh + swoff(n, ks * 2 + b_cb), bh[nb][0], bh[nb][1], bh[nb][2], bh[nb][3]);
                ldsm4(sWl + swoff(n, ks * 2 + b_cb), bl[nb][0], bl[nb][1], bl[nb][2], bl[nb][3]);
            }
#pragma unroll
            for (int mt = 0; mt < 2; ++mt)
#pragma unroll
                for (int n8 = 0; n8 < 4; ++n8) {
                    const int nb = n8 >> 1, hf = (n8 & 1) * 2;
                    mma16816(acc[mt][n8], ah[mt], bh[nb][hf], bh[nb][hf + 1]);
                    mma16816(acc[mt][n8], ah[mt], bl[nb][hf], bl[nb][hf + 1]);
                    mma16816(acc[mt][n8], al[mt], bh[nb][hf], bh[nb][hf + 1]);
                }
        }
        __syncthreads();

        if (c + 2 < 4) {
#pragma unroll
            for (int i = 0; i < 4; ++i) {
                int idx = tid + 256 * i;
                int r = idx >> 4, ch = idx & 15;
                cpasync16(sAh + swoff(r, ch),
                          g_xh + (size_t)(row0 + r) * DIM + (c + 2) * 128 + ch * 8);
                cpasync16(sAl + swoff(r, ch),
                          g_xl + (size_t)(row0 + r) * DIM + (c + 2) * 128 + ch * 8);
            }
#pragma unroll
            for (int i = 0; i < 8; ++i) {
                int idx = tid + 256 * i;
                int r = idx >> 4, ch = idx & 15;
                cpasync16(sWh + swoff(r, ch), g_wh + (size_t)r * DIM + (c + 2) * 128 + ch * 8);
                cpasync16(sWl + swoff(r, ch), g_wl + (size_t)r * DIM + (c + 2) * 128 + ch * 8);
            }
        }
        asm volatile("cp.async.commit_group;" ::: "memory");
    }

    float rsv[2][2], muv[2][2];
#pragma unroll
    for (int mt = 0; mt < 2; ++mt)
#pragma unroll
        for (int half = 0; half < 2; ++half) {
            int row = row0 + wm0 + mt * 16 + (lane >> 2) + half * 8;
            rsv[mt][half] = g_rs[row];
            muv[mt][half] = g_mu[row];
        }

#pragma unroll
    for (int n8 = 0; n8 < 4; ++n8) {
        int e0 = wn0 + n8 * 8 + (lane & 3) * 2;
        float c10 = g_c1[e0],          c11 = g_c1[e0 + 1];
        float c20 = g_c2[e0],          c21 = g_c2[e0 + 1];
        float bb0 = bq[e0],            bb1 = bq[e0 + 1];
        float g00 = gamma[e0],         g01 = gamma[e0 + 1];
        float b00 = beta[e0],          b01 = beta[e0 + 1];
        float g10 = gamma[QK + e0],    g11 = gamma[QK + e0 + 1];
        float b10 = beta[QK + e0],     b11 = beta[QK + e0 + 1];
#pragma unroll
        for (int mt = 0; mt < 2; ++mt) {
#pragma unroll
            for (int half = 0; half < 2; ++half) {
                int row = row0 + wm0 + mt * 16 + (lane >> 2) + half * 8;
                float rs = rsv[mt][half], mu = muv[mt][half];
                float z0 = rs * (acc[mt][n8][half * 2]     - mu * c10) + c20 + bb0;
                float z1 = rs * (acc[mt][n8][half * 2 + 1] - mu * c11) + c21 + bb1;
                float v0 = z0 / (1.f + expf(-z0));
                float v1 = z1 / (1.f + expf(-z1));
                float q0 = v0 * g00 + b00, q1 = v1 * g01 + b01;
                float k0 = v0 * g10 + b10, k1 = v1 * g11 + b11;
                __nv_bfloat16 t0, t1;
                size_t off = (size_t)row * QK + e0;
                t0 = __float2bfloat16(q0); t1 = __float2bfloat16(q1);
                *(uint32_t*)(g_qh + off) = (uint32_t)__bfloat16_as_ushort(t0) |
                                           ((uint32_t)__bfloat16_as_ushort(t1) << 16);
                __nv_bfloat16 r0 = __float2bfloat16(q0 - __bfloat162float(t0));
                __nv_bfloat16 r1 = __float2bfloat16(q1 - __bfloat162float(t1));
                *(uint32_t*)(g_ql + off) = (uint32_t)__bfloat16_as_ushort(r0) |
                                           ((uint32_t)__bfloat16_as_ushort(r1) << 16);
                t0 = __float2bfloat16(k0); t1 = __float2bfloat16(k1);
                *(uint32_t*)(g_kh + off) = (uint32_t)__bfloat16_as_ushort(t0) |
                                           ((uint32_t)__bfloat16_as_ushort(t1) << 16);
                r0 = __float2bfloat16(k0 - __bfloat162float(t0));
                r1 = __float2bfloat16(k1 - __bfloat162float(t1));
                *(uint32_t*)(g_kl + off) = (uint32_t)__bfloat16_as_ushort(r0) |
                                           ((uint32_t)__bfloat16_as_ushort(r1) << 16);
            }
        }
    }
}

// ---------------------------------------------------------------------------
// Kernel 2: strip-persistent HMMA sim GEMM; stores RAW dot as fp16 to g_s.
// ---------------------------------------------------------------------------
#define SA_HI 0
#define SA_LO 32768
#define SB0   65536
#define ATT_SMEM 196608

__device__ __forceinline__ void load_tile128_512(uint32_t dst, const __nv_bfloat16* g, int tid) {
#pragma unroll
    for (int i = 0; i < 4; ++i) {
        int idx = tid + 512 * i;
        int r = idx >> 4, ch = idx & 15;
        cpasync16(dst + swoff(r, ch), g + (size_t)r * QK + ch * 8);
    }
}

__global__ __launch_bounds__(512, 1) void attn_kernel()
{
    extern __shared__ char smem[];
    const uint32_t sb = smem_u32(smem);
    const int tid = threadIdx.x, wid = tid >> 5, lane = tid & 31;
    const int b = blockIdx.y, strip = blockIdx.x;
    const size_t brow = (size_t)b * SEQ + strip * 128;

    const __nv_bfloat16* qh = g_qh + brow * QK;
    const __nv_bfloat16* ql = g_ql + brow * QK;
    const __nv_bfloat16* khb = g_kh + (size_t)b * SEQ * QK;
    const __nv_bfloat16* klb = g_kl + (size_t)b * SEQ * QK;

    load_tile128_512(sb + SA_HI, qh, tid);
    load_tile128_512(sb + SA_LO, ql, tid);
    load_tile128_512(sb + SB0,         khb, tid);
    load_tile128_512(sb + SB0 + 32768, klb, tid);
    asm volatile("cp.async.commit_group;" ::: "memory");
    load_tile128_512(sb + SB0 + 65536,         khb + (size_t)128 * QK, tid);
    load_tile128_512(sb + SB0 + 65536 + 32768, klb + (size_t)128 * QK, tid);
    asm volatile("cp.async.commit_group;" ::: "memory");

    const int wm0 = (wid & 3) * 32;
    const int wn0 = (wid >> 2) * 32;
    const int a_r  = wm0 + (lane & 15);
    const int a_cb = lane >> 4;
    const int b_n  = wn0 + (lane & 7) + ((lane & 16) >> 1);
    const int b_cb = (lane >> 3) & 1;

    for (int jt = 0; jt < NJT; ++jt) {
        const int s = jt & 1;
        asm volatile("cp.async.wait_group 1;" ::: "memory");
        __syncthreads();

        const uint32_t sBh = sb + SB0 + s * 65536;
        const uint32_t sBl = sBh + 32768;

        float acc[2][4][4];
#pragma unroll
        for (int mt = 0; mt < 2; ++mt)
#pragma unroll
            for (int n8 = 0; n8 < 4; ++n8)
#pragma unroll
                for (int v = 0; v < 4; ++v) acc[mt][n8][v] = 0.f;

#pragma unroll
        for (int ks = 0; ks < 8; ++ks) {
            uint32_t ah[2][4], al[2][4];
#pragma unroll
            for (int mt = 0; mt < 2; ++mt) {
                int r = a_r + mt * 16;
                ldsm4(sb + SA_HI + swoff(r, ks * 2 + a_cb), ah[mt][0], ah[mt][1], ah[mt][2], ah[mt][3]);
                ldsm4(sb + SA_LO + swoff(r, ks * 2 + a_cb), al[mt][0], al[mt][1], al[mt][2], al[mt][3]);
            }
            uint32_t bh[2][4], bl[2][4];
#pragma unroll
            for (int nb = 0; nb < 2; ++nb) {
                int n = b_n + nb * 16;
                ldsm4(sBh + swoff(n, ks * 2 + b_cb), bh[nb][0], bh[nb][1], bh[nb][2], bh[nb][3]);
                ldsm4(sBl + swoff(n, ks * 2 + b_cb), bl[nb][0], bl[nb][1], bl[nb][2], bl[nb][3]);
            }
#pragma unroll
            for (int mt = 0; mt < 2; ++mt)
#pragma unroll
                for (int n8 = 0; n8 < 4; ++n8) {
                    const int nb = n8 >> 1, hf = (n8 & 1) * 2;
                    mma16816(acc[mt][n8], ah[mt], bh[nb][hf], bh[nb][hf + 1]);
                    mma16816(acc[mt][n8], ah[mt], bl[nb][hf], bl[nb][hf + 1]);
                    mma16816(acc[mt][n8], al[mt], bh[nb][hf], bh[nb][hf + 1]);
                }
        }
        __syncthreads();

        if (jt + 2 < NJT) {
            load_tile128_512(sBh, khb + (size_t)(jt + 2) * 128 * QK, tid);
            load_tile128_512(sBl, klb + (size_t)(jt + 2) * 128 * QK, tid);
        }
        asm volatile("cp.async.commit_group;" ::: "memory");

        // epilogue: store RAW dot as fp16 (norm kernel applies relu^2/scale)
#pragma unroll
        for (int mt = 0; mt < 2; ++mt) {
#pragma unroll
            for (int n8 = 0; n8 < 4; ++n8) {
                int grow = wm0 + mt * 16 + (lane >> 2);
                int gcol = jt * 128 + wn0 + n8 * 8 + (lane & 3) * 2;
                __half* p0 = g_s + (brow + grow) * SEQ + gcol;
                __half* p1 = p0 + (size_t)8 * SEQ;
                *(__half2*)p0 = __floats2half2_rn(acc[mt][n8][0], acc[mt][n8][1]);
                *(__half2*)p1 = __floats2half2_rn(acc[mt][n8][2], acc[mt][n8][3]);
            }
        }
    }
}

// ---------------------------------------------------------------------------
// Kernel 3: read fp16 raw dots, relu(s/64)^2, row-normalize, write fp32 out.
// One block per row; 256 threads x 16 halfs each.
// ---------------------------------------------------------------------------
__global__ __launch_bounds__(256) void norm_kernel(float* __restrict__ out)
{
    const size_t row = blockIdx.x;
    const uint4* ps = (const uint4*)(g_s + row * SEQ);   // 8 halfs per uint4
    const int tid = threadIdx.x;

    float v[16];
    float s = 0.f;
#pragma unroll
    for (int i = 0; i < 2; ++i) {
        uint4 h = ps[tid + 256 * i];
        const __half2* hp = (const __half2*)&h;
#pragma unroll
        for (int j = 0; j < 4; ++j) {
            float2 f = __half22float2(hp[j]);
            float t0 = fmaxf(f.x * 0.015625f, 0.f);
            float t1 = fmaxf(f.y * 0.015625f, 0.f);
            v[i * 8 + j * 2]     = t0 * t0;
            v[i * 8 + j * 2 + 1] = t1 * t1;
            s += t0 * t0 + t1 * t1;
        }
    }

    __shared__ float red[256];
    red[tid] = s;
    __syncthreads();
#pragma unroll
    for (int o = 128; o > 0; o >>= 1) {
        if (tid < o) red[tid] += red[tid + o];
        __syncthreads();
    }
    float inv = 1.f / (red[0] + 1e-6f);

#pragma unroll
    for (int i = 0; i < 2; ++i) {
        float4 o0, o1;
        o0.x = v[i * 8 + 0] * inv; o0.y = v[i * 8 + 1] * inv;
        o0.z = v[i * 8 + 2] * inv; o0.w = v[i * 8 + 3] * inv;
        o1.x = v[i * 8 + 4] * inv; o1.y = v[i * 8 + 5] * inv;
        o1.z = v[i * 8 + 6] * inv; o1.w = v[i * 8 + 7] * inv;
        float* op = out + row * SEQ + (tid + 256 * i) * 8;
        *(float4*)op       = o0;
        *(float4*)(op + 4) = o1;
    }
}

// ---------------------------------------------------------------------------
extern "C" void kernel_launch(void* const* d_in, const int* in_sizes, int n_in,
                              void* d_out, int out_size)
{
    const float* x     = (const float*)d_in[0];
    const float* ln_w  = (const float*)d_in[1];
    const float* ln_b  = (const float*)d_in[2];
    const float* w_qk  = (const float*)d_in[3];
    const float* b_qk  = (const float*)d_in[4];
    const float* gamma = (const float*)d_in[5];
    const float* beta  = (const float*)d_in[6];
    float* out = (float*)d_out;

    split_kernel<<<2048 + 128, 256>>>(x, w_qk, ln_w, ln_b);

    cudaFuncSetAttribute(qk_kernel, cudaFuncAttributeMaxDynamicSharedMemorySize, QK_SMEM);
    qk_kernel<<<(BATCH * SEQ) / 64, 256, QK_SMEM>>>(b_qk, gamma, beta);

    cudaFuncSetAttribute(attn_kernel, cudaFuncAttributeMaxDynamicSharedMemorySize, ATT_SMEM);
    dim3 g2(SEQ / 128, BATCH);
    attn_kernel<<<g2, 512, ATT_SMEM>>>();

    norm_kernel<<<BATCH * SEQ, 256>>>(out);
}